// round 2
// baseline (speedup 1.0000x reference)
#include <cuda_runtime.h>
#include <math.h>

// ---------------- problem constants ----------------
#define BB   16
#define SS   576
#define DD   768
#define NH   12
#define DK   64
#define FFH  3072
#define NL   6
#define NTOK (BB*SS)            // 9216
#define BSD  (BB*SS*DD)         // 7,077,888

// ---------------- scratch (device globals; no allocation allowed) ----------
__device__ float g_im2col[BSD];
__device__ float g_emb[BSD];
__device__ float g_x[BSD];
__device__ float g_q[BSD];
__device__ float g_k[BSD];
__device__ float g_v[BSD];
__device__ float g_hv[BSD];
__device__ float g_scores[BB*NH*SS*SS];   // 63.7M floats
__device__ float g_x1[BSD];
__device__ float g_xn[BSD];
__device__ float g_ffh[NTOK*FFH];

// ---------------- generic tiled SGEMM ----------------
// C[m,n] = act(alpha * sum_k A[m,k]*B[k,n] + bias) + res
// B optionally stored transposed ([N,K] row-major).
// Batched over blockIdx.z with two-level offsets (zb = z/nh, zh = z%nh).
#define BM 128
#define BN 128
#define BK 8
#define TM 8
#define TN 8

__global__ __launch_bounds__(256) void sgemm_k(
    const float* __restrict__ A, int lda, long long sAb, long long sAh,
    const float* __restrict__ Bm, int ldb, long long sBb, long long sBh, int transB,
    float* __restrict__ C, int ldc, long long sCb, long long sCh,
    const float* __restrict__ res,
    const float* __restrict__ bias, int biasMode,   // 0 none, 1 per-n, 2 per-m
    int M, int N, int K, int nh, float alpha, int act) // act: 0 none, 1 tanh, 2 gelu
{
    int z  = blockIdx.z;
    int zb = z / nh, zh = z % nh;
    A  += (long long)zb * sAb + (long long)zh * sAh;
    Bm += (long long)zb * sBb + (long long)zh * sBh;
    C  += (long long)zb * sCb + (long long)zh * sCh;

    __shared__ float As[BK][BM];
    __shared__ float Bs[BK][BN];

    const int tid = threadIdx.x;
    const int m0 = blockIdx.y * BM;
    const int n0 = blockIdx.x * BN;
    const int tx = tid % 16;
    const int ty = tid / 16;

    float acc[TM][TN];
    #pragma unroll
    for (int i = 0; i < TM; i++)
        #pragma unroll
        for (int j = 0; j < TN; j++) acc[i][j] = 0.f;

    const int arow = tid >> 1;          // 0..127
    const int acol = (tid & 1) * 4;     // 0 or 4
    const int brow = tid >> 5;          // 0..7   (k) for non-trans
    const int bcol = (tid & 31) * 4;    // 0..124 (n) for non-trans
    const int trow = tid >> 1;          // 0..127 (n) for trans
    const int tcol = (tid & 1) * 4;     // 0 or 4 (k) for trans

    for (int k0 = 0; k0 < K; k0 += BK) {
        // A tile (128 x 8), stored transposed in smem
        float4 av = make_float4(0.f, 0.f, 0.f, 0.f);
        if (m0 + arow < M)
            av = *(const float4*)(A + (long long)(m0 + arow) * lda + k0 + acol);
        As[acol + 0][arow] = av.x;
        As[acol + 1][arow] = av.y;
        As[acol + 2][arow] = av.z;
        As[acol + 3][arow] = av.w;

        // B tile (8 x 128)
        if (!transB) {
            float4 bv = make_float4(0.f, 0.f, 0.f, 0.f);
            if (n0 + bcol < N)
                bv = *(const float4*)(Bm + (long long)(k0 + brow) * ldb + n0 + bcol);
            Bs[brow][bcol + 0] = bv.x;
            Bs[brow][bcol + 1] = bv.y;
            Bs[brow][bcol + 2] = bv.z;
            Bs[brow][bcol + 3] = bv.w;
        } else {
            float4 bv = make_float4(0.f, 0.f, 0.f, 0.f);
            if (n0 + trow < N)
                bv = *(const float4*)(Bm + (long long)(n0 + trow) * ldb + k0 + tcol);
            Bs[tcol + 0][trow] = bv.x;
            Bs[tcol + 1][trow] = bv.y;
            Bs[tcol + 2][trow] = bv.z;
            Bs[tcol + 3][trow] = bv.w;
        }
        __syncthreads();

        #pragma unroll
        for (int kk = 0; kk < BK; kk++) {
            float ar[TM], br[TN];
            #pragma unroll
            for (int i = 0; i < TM; i++) ar[i] = As[kk][ty * TM + i];
            #pragma unroll
            for (int j = 0; j < TN; j++) br[j] = Bs[kk][tx * TN + j];
            #pragma unroll
            for (int i = 0; i < TM; i++)
                #pragma unroll
                for (int j = 0; j < TN; j++) acc[i][j] += ar[i] * br[j];
        }
        __syncthreads();
    }

    #pragma unroll
    for (int i = 0; i < TM; i++) {
        int m = m0 + ty * TM + i;
        if (m >= M) continue;
        #pragma unroll
        for (int j = 0; j < TN; j++) {
            int n = n0 + tx * TN + j;
            if (n >= N) continue;
            float vv = alpha * acc[i][j];
            if (biasMode == 1)      vv += bias[n];
            else if (biasMode == 2) vv += bias[m];
            if (act == 1)      vv = tanhf(vv);
            else if (act == 2) vv = 0.5f * vv * (1.0f + erff(vv * 0.70710678118654752f));
            if (res) vv += res[(long long)m * ldc + n];
            C[(long long)m * ldc + n] = vv;
        }
    }
}

// ---------------- im2col for patch embedding ----------------
// out[(b*576+p)*768 + k], p = py*24+px, k = c*256 + ph*16 + pw
__global__ void im2col_k(const float* __restrict__ x, float* __restrict__ out) {
    int i = blockIdx.x * blockDim.x + threadIdx.x;
    if (i >= BSD) return;
    int b = i / (SS * DD);
    int r = i % (SS * DD);
    int p = r / DD;
    int k = r % DD;
    int c  = k >> 8;
    int ph = (k >> 4) & 15;
    int pw = k & 15;
    int py = p / 24;
    int px = p % 24;
    out[i] = x[(((long long)(b * 3 + c) * 384) + (py * 16 + ph)) * 384 + (px * 16 + pw)];
}

// ---------------- PE add: x = emb + pos_encoding ----------------
__global__ void pe_add_k(const float* __restrict__ emb, float* __restrict__ x) {
    int i = blockIdx.x * blockDim.x + threadIdx.x;
    if (i >= BSD) return;
    int r = i % (SS * DD);
    int t = r / DD;
    int d = r % DD;
    int j2 = (d >> 1) * 2;
    // div = exp(-j2 * ln(10000)/768)
    float div = expf(-(float)j2 * (9.210340371976184f / 768.0f));
    float ang = (float)t * div;
    float pe = (d & 1) ? cosf(ang) : sinf(ang);
    x[i] = emb[i] + pe;
}

// ---------------- softmax: warp per row of length SS ----------------
__global__ void softmax_k(float* __restrict__ data, int rows) {
    int warp = (blockIdx.x * blockDim.x + threadIdx.x) >> 5;
    if (warp >= rows) return;
    int lane = threadIdx.x & 31;
    float* p = data + (long long)warp * SS;

    float mx = -1e30f;
    for (int c = lane; c < SS; c += 32) mx = fmaxf(mx, p[c]);
    #pragma unroll
    for (int o = 16; o > 0; o >>= 1) mx = fmaxf(mx, __shfl_xor_sync(0xffffffff, mx, o));

    float sum = 0.f;
    for (int c = lane; c < SS; c += 32) {
        float e = expf(p[c] - mx);
        p[c] = e;
        sum += e;
    }
    #pragma unroll
    for (int o = 16; o > 0; o >>= 1) sum += __shfl_xor_sync(0xffffffff, sum, o);
    float inv = 1.0f / sum;
    for (int c = lane; c < SS; c += 32) p[c] *= inv;
}

// ---------------- layernorm: block per row of 768 ----------------
__global__ void ln_k(const float* __restrict__ in, float* __restrict__ out,
                     const float* __restrict__ sc, const float* __restrict__ bi,
                     float eps) {
    int row = blockIdx.x;
    const float* p = in + (long long)row * DD;
    float*       o = out + (long long)row * DD;
    int tid = threadIdx.x;  // 256

    float v0 = p[tid], v1 = p[tid + 256], v2 = p[tid + 512];

    __shared__ float red[256];
    red[tid] = v0 + v1 + v2;
    __syncthreads();
    #pragma unroll
    for (int st = 128; st > 0; st >>= 1) {
        if (tid < st) red[tid] += red[tid + st];
        __syncthreads();
    }
    float mean = red[0] * (1.0f / DD);
    __syncthreads();

    float d0 = v0 - mean, d1 = v1 - mean, d2 = v2 - mean;
    red[tid] = d0 * d0 + d1 * d1 + d2 * d2;
    __syncthreads();
    #pragma unroll
    for (int st = 128; st > 0; st >>= 1) {
        if (tid < st) red[tid] += red[tid + st];
        __syncthreads();
    }
    float inv = rsqrtf(red[0] * (1.0f / DD) + eps);

    o[tid]       = d0 * inv * sc[tid]       + bi[tid];
    o[tid + 256] = d1 * inv * sc[tid + 256] + bi[tid + 256];
    o[tid + 512] = d2 * inv * sc[tid + 512] + bi[tid + 512];
}

// ---------------- host-side helpers ----------------
static void gemm(const float* A, int lda, long long sAb, long long sAh,
                 const float* Bm, int ldb, long long sBb, long long sBh, int transB,
                 float* C, int ldc, long long sCb, long long sCh,
                 const float* res, const float* bias, int biasMode,
                 int M, int N, int K, int batches, int nh, float alpha, int act) {
    dim3 grid((N + BN - 1) / BN, (M + BM - 1) / BM, batches);
    sgemm_k<<<grid, 256>>>(A, lda, sAb, sAh, Bm, ldb, sBb, sBh, transB,
                           C, ldc, sCb, sCh, res, bias, biasMode,
                           M, N, K, nh, alpha, act);
}

extern "C" void kernel_launch(void* const* d_in, const int* in_sizes, int n_in,
                              void* d_out, int out_size) {
    const float* x      = (const float*)d_in[0];
    const float* conv_w = (const float*)d_in[1];
    const float* conv_b = (const float*)d_in[2];
    // ln1_s = d_in[3], ln1_b = d_in[4]  -> unused by reference (bug kept faithful)
    const float* wq   = (const float*)d_in[5];
    const float* wk   = (const float*)d_in[6];
    const float* wv   = (const float*)d_in[7];
    const float* wh   = (const float*)d_in[8];
    const float* wh_b = (const float*)d_in[9];
    const float* ln2_s = (const float*)d_in[10];
    const float* ln2_b = (const float*)d_in[11];
    const float* w1   = (const float*)d_in[12];
    const float* b1   = (const float*)d_in[13];
    const float* w2   = (const float*)d_in[14];
    const float* b2   = (const float*)d_in[15];
    const float* lnf_s = (const float*)d_in[16];
    const float* lnf_b = (const float*)d_in[17];
    float* out = (float*)d_out;

    float *p_im2col, *p_emb, *p_x, *p_q, *p_k, *p_v, *p_hv, *p_sc, *p_x1, *p_xn, *p_ffh;
    cudaGetSymbolAddress((void**)&p_im2col, g_im2col);
    cudaGetSymbolAddress((void**)&p_emb,    g_emb);
    cudaGetSymbolAddress((void**)&p_x,      g_x);
    cudaGetSymbolAddress((void**)&p_q,      g_q);
    cudaGetSymbolAddress((void**)&p_k,      g_k);
    cudaGetSymbolAddress((void**)&p_v,      g_v);
    cudaGetSymbolAddress((void**)&p_hv,     g_hv);
    cudaGetSymbolAddress((void**)&p_sc,     g_scores);
    cudaGetSymbolAddress((void**)&p_x1,     g_x1);
    cudaGetSymbolAddress((void**)&p_xn,     g_xn);
    cudaGetSymbolAddress((void**)&p_ffh,    g_ffh);

    const int threads = 256;

    // 1) im2col
    im2col_k<<<(BSD + threads - 1) / threads, threads>>>(x, p_im2col);

    // 2) patch GEMM: emb[b][d'][p] = tanh( W[d',:] . im2col_b[p,:] + conv_b[d'] )
    //    per batch: M=768 (d'), N=576 (p), K=768; B transposed ([N,K]).
    gemm(conv_w, DD, 0, 0,
         p_im2col, DD, (long long)SS * DD, 0, 1,
         p_emb, SS, (long long)DD * SS, 0,
         nullptr, conv_b, 2,
         DD, SS, DD, BB, 1, 1.0f, 1 /*tanh*/);

    // 3) x = emb(flat) + PE   (faithful NCHW reshape: flat index within batch IS t*768+d)
    pe_add_k<<<(BSD + threads - 1) / threads, threads>>>(p_emb, p_x);

    const long long sBS = (long long)SS * DD;       // per-batch stride in token tensors
    const long long sSC_b = (long long)NH * SS * SS;
    const long long sSC_h = (long long)SS * SS;

    for (int l = 0; l < NL; l++) {
        const float* wql = wq + (long long)l * DD * DD;
        const float* wkl = wk + (long long)l * DD * DD;
        const float* wvl = wv + (long long)l * DD * DD;
        const float* whl = wh + (long long)l * DD * DD;
        const float* whbl = wh_b + (long long)l * DD;
        const float* w1l = w1 + (long long)l * DD * FFH;
        const float* b1l = b1 + (long long)l * FFH;
        const float* w2l = w2 + (long long)l * FFH * DD;
        const float* b2l = b2 + (long long)l * DD;
        const float* s2l = ln2_s + (long long)l * DD;
        const float* bb2l = ln2_b + (long long)l * DD;

        // Q,K,V: [9216,768] x [768,768]
        gemm(p_x, DD, 0, 0, wql, DD, 0, 0, 0, p_q, DD, 0, 0,
             nullptr, nullptr, 0, NTOK, DD, DD, 1, 1, 1.0f, 0);
        gemm(p_x, DD, 0, 0, wkl, DD, 0, 0, 0, p_k, DD, 0, 0,
             nullptr, nullptr, 0, NTOK, DD, DD, 1, 1, 1.0f, 0);
        gemm(p_x, DD, 0, 0, wvl, DD, 0, 0, 0, p_v, DD, 0, 0,
             nullptr, nullptr, 0, NTOK, DD, DD, 1, 1, 1.0f, 0);

        // scores[b,h] = (1/8) * Qh (576x64) . Kh^T : batched over 192
        gemm(p_q, DD, sBS, DK,
             p_k, DD, sBS, DK, 1 /*transB*/,
             p_sc, SS, sSC_b, sSC_h,
             nullptr, nullptr, 0,
             SS, SS, DK, BB * NH, NH, 0.125f, 0);

        // softmax over rows
        {
            int rows = BB * NH * SS;          // 110592
            int blocks = (rows * 32 + 255) / 256;
            softmax_k<<<blocks, 256>>>(p_sc, rows);
        }

        // hv[b,:,h*64+n] = scores[b,h] . Vh : M=576,N=64,K=576, batched 192
        gemm(p_sc, SS, sSC_b, sSC_h,
             p_v, DD, sBS, DK, 0,
             p_hv, DD, sBS, DK,
             nullptr, nullptr, 0,
             SS, DK, SS, BB * NH, NH, 1.0f, 0);

        // x1 = hv . wh + wh_b + x
        gemm(p_hv, DD, 0, 0, whl, DD, 0, 0, 0, p_x1, DD, 0, 0,
             p_x, whbl, 1, NTOK, DD, DD, 1, 1, 1.0f, 0);

        // xn = LN(x1), eps=1e-6
        ln_k<<<NTOK, 256>>>(p_x1, p_xn, s2l, bb2l, 1e-6f);

        // ffh = gelu(xn . w1 + b1)
        gemm(p_xn, DD, 0, 0, w1l, FFH, 0, 0, 0, p_ffh, FFH, 0, 0,
             nullptr, b1l, 1, NTOK, FFH, DD, 1, 1, 1.0f, 2 /*gelu*/);

        // x = ffh . w2 + b2 + x1
        gemm(p_ffh, FFH, 0, 0, w2l, DD, 0, 0, 0, p_x, DD, 0, 0,
             p_x1, b2l, 1, NTOK, DD, FFH, 1, 1, 1.0f, 0);
    }

    // final LN, eps=1e-12, straight to output
    ln_k<<<NTOK, 256>>>(p_x, out, lnf_s, lnf_b, 1e-12f);
}

// round 6
// speedup vs baseline: 2.1003x; 2.1003x over previous
#include <cuda_runtime.h>
#include <math.h>
#include <stdint.h>

#define BB   16
#define SS   576
#define DD   768
#define NH   12
#define DK   64
#define FFH  3072
#define NL   6
#define NTOK (BB*SS)
#define BSD  (BB*SS*DD)

typedef unsigned short u16;

// ---------------- scratch ----------------
__device__ float g_emb[BSD];
__device__ float g_x[BSD];
__device__ float g_q[BSD];
__device__ float g_k[BSD];
__device__ float g_v[BSD];
__device__ float g_hv[BSD];
__device__ float g_x1[BSD];
__device__ float g_xn[BSD];
__device__ float g_scores[BB*NH*SS*SS];
__device__ float g_ffh[NTOK*FFH];
__device__ u16 g_i2h[BSD],  g_i2l[BSD];
__device__ u16 g_vth[BB*NH*DK*SS], g_vtl[BB*NH*DK*SS];
__device__ u16 g_wqth[NL*DD*DD],  g_wqtl[NL*DD*DD];
__device__ u16 g_wkth[NL*DD*DD],  g_wktl[NL*DD*DD];
__device__ u16 g_wvth[NL*DD*DD],  g_wvtl[NL*DD*DD];
__device__ u16 g_whth[NL*DD*DD],  g_whtl[NL*DD*DD];
__device__ u16 g_w1th[NL*DD*FFH], g_w1tl[NL*DD*FFH];
__device__ u16 g_w2th[NL*DD*FFH], g_w2tl[NL*DD*FFH];

__device__ __forceinline__ uint32_t bf16rn(float x) {
    uint32_t b = __float_as_uint(x);
    return (b + 0x7FFFu + ((b >> 16) & 1u)) >> 16;
}
__device__ __forceinline__ float bfval(uint32_t h) { return __uint_as_float(h << 16); }

__device__ __forceinline__ void mma16816(float* c, const uint32_t* a, const uint32_t* b) {
    asm volatile(
        "mma.sync.aligned.m16n8k16.row.col.f32.bf16.bf16.f32 "
        "{%0,%1,%2,%3}, {%4,%5,%6,%7}, {%8,%9}, {%0,%1,%2,%3};"
        : "+f"(c[0]), "+f"(c[1]), "+f"(c[2]), "+f"(c[3])
        : "r"(a[0]), "r"(a[1]), "r"(a[2]), "r"(a[3]), "r"(b[0]), "r"(b[1]));
}

// ---------------- mma.sync GEMM ----------------
// D[m,n] = act(alpha*sum_k A[m,k]*B[n,k] + bias) + res
// A fp32 [M,K]; B fp32 [N,K] or pre-split bf16 hi/lo [N,K]. Split-3 bf16.
#define BKC 32
#define ASTRIDE 34
#define OFF_AL  (128*ASTRIDE)
#define OFF_BH  (2*128*ASTRIDE)
#define OFF_BL  (3*128*ASTRIDE)
#define STAGE_U16 (4*128*ASTRIDE)
#define SMEM_DYN (2*STAGE_U16*2)   // 69632 bytes

__device__ __forceinline__ void split_store(u16* baseH, u16* baseL, int r, int k, float4 v) {
    uint32_t h0 = bf16rn(v.x), h1 = bf16rn(v.y), h2 = bf16rn(v.z), h3 = bf16rn(v.w);
    uint32_t l0 = bf16rn(v.x - bfval(h0)), l1 = bf16rn(v.y - bfval(h1));
    uint32_t l2 = bf16rn(v.z - bfval(h2)), l3 = bf16rn(v.w - bfval(h3));
    uint32_t* pH = (uint32_t*)(baseH + r * ASTRIDE + k);
    pH[0] = h0 | (h1 << 16); pH[1] = h2 | (h3 << 16);
    uint32_t* pL = (uint32_t*)(baseL + r * ASTRIDE + k);
    pL[0] = l0 | (l1 << 16); pL[1] = l2 | (l3 << 16);
}

__global__ __launch_bounds__(256) void mma_gemm(
    const float* __restrict__ A, int lda, long long sAb, long long sAh,
    const float* __restrict__ Bf,
    const u16* __restrict__ Bsh, const u16* __restrict__ Bsl,
    int ldb, long long sBb, long long sBhh,
    float* __restrict__ C, int ldc, long long sCb, long long sCh,
    const float* __restrict__ res, const float* __restrict__ bias, int biasMode,
    int M, int N, int K, int nh, float alpha, int act)
{
    extern __shared__ __align__(16) u16 smem[];
    const int tid = threadIdx.x;
    const int wid = tid >> 5, lane = tid & 31;
    const int wm = wid >> 2, wn = wid & 3;
    const int gid = lane >> 2, tig = lane & 3;

    int z = blockIdx.z, zb = z / nh, zh = z - zb * nh;
    A += zb * sAb + zh * sAh;
    if (Bf)  Bf  += zb * sBb + zh * sBhh;
    if (Bsh) { Bsh += zb * sBb + zh * sBhh; Bsl += zb * sBb + zh * sBhh; }
    C += zb * sCb + zh * sCh;
    const float* resT = res ? res + zb * sCb + zh * sCh : nullptr;

    const int m0 = blockIdx.y * 128;
    const int n0 = blockIdx.x * 128;
    int validM = M - m0; if (validM > 128) validM = 128;
    int validN = N - n0; if (validN > 128) validN = 128;
    const float* At = A + (long long)m0 * lda;
    const float* Bft = Bf ? Bf + (long long)n0 * ldb : nullptr;
    const u16* Bht = Bsh ? Bsh + (long long)n0 * ldb : nullptr;
    const u16* Blt = Bsl ? Bsl + (long long)n0 * ldb : nullptr;

    const int lr = tid >> 3;        // 0..31, row per iter
    const int lk = (tid & 7) * 4;   // 0..28

    float acc[4][4][4];
    #pragma unroll
    for (int i = 0; i < 4; i++)
        #pragma unroll
        for (int j = 0; j < 4; j++)
            #pragma unroll
            for (int q = 0; q < 4; q++) acc[i][j][q] = 0.f;

    const int nC = K / BKC;

    float4 pa[4];
    uint2 pbh[4], pbl[4];
    float4 pbf[4];

    // fetch chunk 0
    #pragma unroll
    for (int it = 0; it < 4; ++it) {
        int r = it * 32 + lr;
        pa[it] = (r < validM) ? *(const float4*)(At + (long long)r * lda + lk)
                              : make_float4(0.f, 0.f, 0.f, 0.f);
        if (Bht) {
            if (r < validN) {
                pbh[it] = *(const uint2*)(Bht + (long long)r * ldb + lk);
                pbl[it] = *(const uint2*)(Blt + (long long)r * ldb + lk);
            } else { pbh[it] = make_uint2(0u, 0u); pbl[it] = make_uint2(0u, 0u); }
        } else {
            pbf[it] = (r < validN) ? *(const float4*)(Bft + (long long)r * ldb + lk)
                                   : make_float4(0.f, 0.f, 0.f, 0.f);
        }
    }
    // store stage 0
    {
        u16* st = smem;
        #pragma unroll
        for (int it = 0; it < 4; ++it) {
            int r = it * 32 + lr;
            split_store(st, st + OFF_AL, r, lk, pa[it]);
            if (Bht) {
                uint32_t* pH = (uint32_t*)(st + OFF_BH + r * ASTRIDE + lk);
                pH[0] = pbh[it].x; pH[1] = pbh[it].y;
                uint32_t* pL = (uint32_t*)(st + OFF_BL + r * ASTRIDE + lk);
                pL[0] = pbl[it].x; pL[1] = pbl[it].y;
            } else {
                split_store(st + OFF_BH, st + OFF_BL, r, lk, pbf[it]);
            }
        }
    }
    __syncthreads();

    for (int c = 0; c < nC; ++c) {
        // prefetch chunk c+1 into regs
        if (c + 1 < nC) {
            int k0 = (c + 1) * BKC;
            #pragma unroll
            for (int it = 0; it < 4; ++it) {
                int r = it * 32 + lr;
                pa[it] = (r < validM) ? *(const float4*)(At + (long long)r * lda + k0 + lk)
                                      : make_float4(0.f, 0.f, 0.f, 0.f);
                if (Bht) {
                    if (r < validN) {
                        pbh[it] = *(const uint2*)(Bht + (long long)r * ldb + k0 + lk);
                        pbl[it] = *(const uint2*)(Blt + (long long)r * ldb + k0 + lk);
                    } else { pbh[it] = make_uint2(0u, 0u); pbl[it] = make_uint2(0u, 0u); }
                } else {
                    pbf[it] = (r < validN) ? *(const float4*)(Bft + (long long)r * ldb + k0 + lk)
                                           : make_float4(0.f, 0.f, 0.f, 0.f);
                }
            }
        }

        // compute from stage c&1
        const u16* sA  = smem + (c & 1) * STAGE_U16;
        const u16* sAl = sA + OFF_AL;
        const u16* sBh = sA + OFF_BH;
        const u16* sBl = sA + OFF_BL;
        #pragma unroll
        for (int kk = 0; kk < 32; kk += 16) {
            uint32_t ah[4][4], al[4][4], bh[4][2], bl[4][2];
            #pragma unroll
            for (int i = 0; i < 4; ++i) {
                int rb = (wm * 64 + i * 16 + gid) * ASTRIDE + kk + tig * 2;
                ah[i][0] = *(const uint32_t*)(sA + rb);
                ah[i][1] = *(const uint32_t*)(sA + rb + 8 * ASTRIDE);
                ah[i][2] = *(const uint32_t*)(sA + rb + 8);
                ah[i][3] = *(const uint32_t*)(sA + rb + 8 * ASTRIDE + 8);
                al[i][0] = *(const uint32_t*)(sAl + rb);
                al[i][1] = *(const uint32_t*)(sAl + rb + 8 * ASTRIDE);
                al[i][2] = *(const uint32_t*)(sAl + rb + 8);
                al[i][3] = *(const uint32_t*)(sAl + rb + 8 * ASTRIDE + 8);
            }
            #pragma unroll
            for (int j = 0; j < 4; ++j) {
                int rb = (wn * 32 + j * 8 + gid) * ASTRIDE + kk + tig * 2;
                bh[j][0] = *(const uint32_t*)(sBh + rb);
                bh[j][1] = *(const uint32_t*)(sBh + rb + 8);
                bl[j][0] = *(const uint32_t*)(sBl + rb);
                bl[j][1] = *(const uint32_t*)(sBl + rb + 8);
            }
            #pragma unroll
            for (int i = 0; i < 4; ++i)
                #pragma unroll
                for (int j = 0; j < 4; ++j) mma16816(acc[i][j], ah[i], bh[j]);
            #pragma unroll
            for (int i = 0; i < 4; ++i)
                #pragma unroll
                for (int j = 0; j < 4; ++j) mma16816(acc[i][j], ah[i], bl[j]);
            #pragma unroll
            for (int i = 0; i < 4; ++i)
                #pragma unroll
                for (int j = 0; j < 4; ++j) mma16816(acc[i][j], al[i], bh[j]);
        }
        __syncthreads();

        // store prefetched chunk
        if (c + 1 < nC) {
            u16* st = smem + ((c + 1) & 1) * STAGE_U16;
            #pragma unroll
            for (int it = 0; it < 4; ++it) {
                int r = it * 32 + lr;
                split_store(st, st + OFF_AL, r, lk, pa[it]);
                if (Bht) {
                    uint32_t* pH = (uint32_t*)(st + OFF_BH + r * ASTRIDE + lk);
                    pH[0] = pbh[it].x; pH[1] = pbh[it].y;
                    uint32_t* pL = (uint32_t*)(st + OFF_BL + r * ASTRIDE + lk);
                    pL[0] = pbl[it].x; pL[1] = pbl[it].y;
                } else {
                    split_store(st + OFF_BH, st + OFF_BL, r, lk, pbf[it]);
                }
            }
            __syncthreads();
        }
    }

    // epilogue
    #pragma unroll
    for (int i = 0; i < 4; ++i) {
        #pragma unroll
        for (int j = 0; j < 4; ++j) {
            int col = n0 + wn * 32 + j * 8 + tig * 2;
            if (col >= N) continue;
            #pragma unroll
            for (int h = 0; h < 2; ++h) {
                int row = m0 + wm * 64 + i * 16 + gid + h * 8;
                if (row >= M) continue;
                float vx = alpha * acc[i][j][h * 2 + 0];
                float vy = alpha * acc[i][j][h * 2 + 1];
                if (biasMode == 1) { vx += bias[col]; vy += bias[col + 1]; }
                else if (biasMode == 2) { float bm = bias[row]; vx += bm; vy += bm; }
                if (act == 1) { vx = tanhf(vx); vy = tanhf(vy); }
                else if (act == 2) {
                    const float s = 0.70710678118654752f;
                    vx = 0.5f * vx * (1.0f + erff(vx * s));
                    vy = 0.5f * vy * (1.0f + erff(vy * s));
                }
                if (resT) {
                    float2 rv = *(const float2*)(resT + (long long)row * ldc + col);
                    vx += rv.x; vy += rv.y;
                }
                float2 o; o.x = vx; o.y = vy;
                *(float2*)(C + (long long)row * ldc + col) = o;
            }
        }
    }
}

// ---------------- aux kernels ----------------
__global__ void im2col_split_k(const float* __restrict__ x,
                               u16* __restrict__ oh, u16* __restrict__ ol) {
    int i = blockIdx.x * blockDim.x + threadIdx.x;
    if (i >= BSD) return;
    int b = i / (SS * DD);
    int r = i % (SS * DD);
    int p = r / DD, k = r % DD;
    int c = k >> 8, ph = (k >> 4) & 15, pw = k & 15;
    int py = p / 24, px = p % 24;
    float v = x[(((long long)(b * 3 + c) * 384) + (py * 16 + ph)) * 384 + (px * 16 + pw)];
    uint32_t h = bf16rn(v);
    oh[i] = (u16)h;
    ol[i] = (u16)bf16rn(v - bfval(h));
}

// [K,N] fp32 -> [N,K] bf16 hi/lo per layer z
__global__ void transp_split_k(const float* __restrict__ in,
                               u16* __restrict__ oh, u16* __restrict__ ol,
                               int K, int N) {
    __shared__ float t[32][33];
    long long zo = (long long)blockIdx.z * K * N;
    int kb = blockIdx.y * 32, nb = blockIdx.x * 32;
    int tx = threadIdx.x, ty = threadIdx.y;
    for (int dy = ty; dy < 32; dy += 8)
        t[dy][tx] = in[zo + (long long)(kb + dy) * N + nb + tx];
    __syncthreads();
    for (int dy = ty; dy < 32; dy += 8) {
        float v = t[tx][dy];
        long long idx = zo + (long long)(nb + dy) * K + kb + tx;
        uint32_t h = bf16rn(v);
        oh[idx] = (u16)h;
        ol[idx] = (u16)bf16rn(v - bfval(h));
    }
}

// v fp32 [b, kpos, h*64+dk] -> vt bf16 [(b*NH+h), dk, kpos]
__global__ void vtrans_k(const float* __restrict__ v,
                         u16* __restrict__ oh, u16* __restrict__ ol) {
    __shared__ float t[32][33];
    int z = blockIdx.z;
    int b = z / NH, hh = z - b * NH;
    int kb = blockIdx.x * 32, db = blockIdx.y * 32;
    int tx = threadIdx.x, ty = threadIdx.y;
    for (int dy = ty; dy < 32; dy += 8)
        t[dy][tx] = v[((long long)(b * SS + kb + dy)) * DD + hh * DK + db + tx];
    __syncthreads();
    for (int dy = ty; dy < 32; dy += 8) {
        float val = t[tx][dy];
        long long idx = ((long long)z * DK + db + dy) * SS + kb + tx;
        uint32_t h = bf16rn(val);
        oh[idx] = (u16)h;
        ol[idx] = (u16)bf16rn(val - bfval(h));
    }
}

__global__ void pe_add_k(const float* __restrict__ emb, float* __restrict__ x) {
    int i = blockIdx.x * blockDim.x + threadIdx.x;
    if (i >= BSD) return;
    int r = i % (SS * DD);
    int t = r / DD, d = r % DD;
    int j2 = (d >> 1) * 2;
    float div = expf(-(float)j2 * (9.210340371976184f / 768.0f));
    float ang = (float)t * div;
    float pe = (d & 1) ? cosf(ang) : sinf(ang);
    x[i] = emb[i] + pe;
}

__global__ void softmax_k(float* __restrict__ data, int rows) {
    int warp = (blockIdx.x * blockDim.x + threadIdx.x) >> 5;
    if (warp >= rows) return;
    int lane = threadIdx.x & 31;
    float* p = data + (long long)warp * SS;
    float r[18];
    #pragma unroll
    for (int j = 0; j < 18; j++) r[j] = p[lane + j * 32];
    float mx = r[0];
    #pragma unroll
    for (int j = 1; j < 18; j++) mx = fmaxf(mx, r[j]);
    #pragma unroll
    for (int o = 16; o > 0; o >>= 1) mx = fmaxf(mx, __shfl_xor_sync(0xffffffff, mx, o));
    float sum = 0.f;
    #pragma unroll
    for (int j = 0; j < 18; j++) { r[j] = expf(r[j] - mx); sum += r[j]; }
    #pragma unroll
    for (int o = 16; o > 0; o >>= 1) sum += __shfl_xor_sync(0xffffffff, sum, o);
    float inv = 1.0f / sum;
    #pragma unroll
    for (int j = 0; j < 18; j++) p[lane + j * 32] = r[j] * inv;
}

__global__ void ln_k(const float* __restrict__ in, float* __restrict__ out,
                     const float* __restrict__ sc, const float* __restrict__ bi, float eps) {
    int row = blockIdx.x;
    const float* p = in + (long long)row * DD;
    float*       o = out + (long long)row * DD;
    int tid = threadIdx.x;
    float v0 = p[tid], v1 = p[tid + 256], v2 = p[tid + 512];
    __shared__ float red[256];
    red[tid] = v0 + v1 + v2;
    __syncthreads();
    #pragma unroll
    for (int st = 128; st > 0; st >>= 1) { if (tid < st) red[tid] += red[tid + st]; __syncthreads(); }
    float mean = red[0] * (1.0f / DD);
    __syncthreads();
    float d0 = v0 - mean, d1 = v1 - mean, d2 = v2 - mean;
    red[tid] = d0 * d0 + d1 * d1 + d2 * d2;
    __syncthreads();
    #pragma unroll
    for (int st = 128; st > 0; st >>= 1) { if (tid < st) red[tid] += red[tid + st]; __syncthreads(); }
    float inv = rsqrtf(red[0] * (1.0f / DD) + eps);
    o[tid]       = d0 * inv * sc[tid]       + bi[tid];
    o[tid + 256] = d1 * inv * sc[tid + 256] + bi[tid + 256];
    o[tid + 512] = d2 * inv * sc[tid + 512] + bi[tid + 512];
}

// ---------------- host helper ----------------
static void mgemm(const float* A, int lda, long long sAb, long long sAh,
                  const float* Bf, const u16* Bh, const u16* Bl,
                  int ldb, long long sBb, long long sBh,
                  float* C, int ldc, long long sCb, long long sCh,
                  const float* res, const float* bias, int biasMode,
                  int M, int N, int K, int batches, int nh, float alpha, int act) {
    dim3 grid((N + 127) / 128, (M + 127) / 128, batches);
    mma_gemm<<<grid, 256, SMEM_DYN>>>(A, lda, sAb, sAh, Bf, Bh, Bl, ldb, sBb, sBh,
                                      C, ldc, sCb, sCh, res, bias, biasMode,
                                      M, N, K, nh, alpha, act);
}

extern "C" void kernel_launch(void* const* d_in, const int* in_sizes, int n_in,
                              void* d_out, int out_size) {
    const float* x      = (const float*)d_in[0];
    const float* conv_w = (const float*)d_in[1];
    const float* conv_b = (const float*)d_in[2];
    const float* wq    = (const float*)d_in[5];
    const float* wk    = (const float*)d_in[6];
    const float* wv    = (const float*)d_in[7];
    const float* wh    = (const float*)d_in[8];
    const float* wh_b  = (const float*)d_in[9];
    const float* ln2_s = (const float*)d_in[10];
    const float* ln2_b = (const float*)d_in[11];
    const float* w1    = (const float*)d_in[12];
    const float* b1    = (const float*)d_in[13];
    const float* w2    = (const float*)d_in[14];
    const float* b2    = (const float*)d_in[15];
    const float* lnf_s = (const float*)d_in[16];
    const float* lnf_b = (const float*)d_in[17];
    float* out = (float*)d_out;

    cudaFuncSetAttribute(mma_gemm, cudaFuncAttributeMaxDynamicSharedMemorySize, SMEM_DYN);

    float *p_emb, *p_x, *p_q, *p_k, *p_v, *p_hv, *p_x1, *p_xn, *p_sc, *p_ffh;
    u16 *p_i2h, *p_i2l, *p_vth, *p_vtl;
    u16 *p_wqh, *p_wql, *p_wkh, *p_wkl, *p_wvh, *p_wvl, *p_whh, *p_whl;
    u16 *p_w1h, *p_w1l, *p_w2h, *p_w2l;
    cudaGetSymbolAddress((void**)&p_emb, g_emb);
    cudaGetSymbolAddress((void**)&p_x,   g_x);
    cudaGetSymbolAddress((void**)&p_q,   g_q);
    cudaGetSymbolAddress((void**)&p_k,   g_k);
    cudaGetSymbolAddress((void**)&p_v,   g_v);
    cudaGetSymbolAddress((void**)&p_hv,  g_hv);
    cudaGetSymbolAddress((void**)&p_x1,  g_x1);
    cudaGetSymbolAddress((void**)&p_xn,  g_xn);
    cudaGetSymbolAddress((void**)&p_sc,  g_scores);
    cudaGetSymbolAddress((void**)&p_ffh, g_ffh);
    cudaGetSymbolAddress((void**)&p_i2h, g_i2h);
    cudaGetSymbolAddress((void**)&p_i2l, g_i2l);
    cudaGetSymbolAddress((void**)&p_vth, g_vth);
    cudaGetSymbolAddress((void**)&p_vtl, g_vtl);
    cudaGetSymbolAddress((void**)&p_wqh, g_wqth); cudaGetSymbolAddress((void**)&p_wql, g_wqtl);
    cudaGetSymbolAddress((void**)&p_wkh, g_wkth); cudaGetSymbolAddress((void**)&p_wkl, g_wktl);
    cudaGetSymbolAddress((void**)&p_wvh, g_wvth); cudaGetSymbolAddress((void**)&p_wvl, g_wvtl);
    cudaGetSymbolAddress((void**)&p_whh, g_whth); cudaGetSymbolAddress((void**)&p_whl, g_whtl);
    cudaGetSymbolAddress((void**)&p_w1h, g_w1th); cudaGetSymbolAddress((void**)&p_w1l, g_w1tl);
    cudaGetSymbolAddress((void**)&p_w2h, g_w2th); cudaGetSymbolAddress((void**)&p_w2l, g_w2tl);

    // ---- prep: im2col split + weight transpose/split ----
    im2col_split_k<<<(BSD + 255) / 256, 256>>>(x, p_i2h, p_i2l);
    {
        dim3 blk(32, 8);
        dim3 gdd(DD / 32, DD / 32, NL);
        transp_split_k<<<gdd, blk>>>(wq, p_wqh, p_wql, DD, DD);
        transp_split_k<<<gdd, blk>>>(wk, p_wkh, p_wkl, DD, DD);
        transp_split_k<<<gdd, blk>>>(wv, p_wvh, p_wvl, DD, DD);
        transp_split_k<<<gdd, blk>>>(wh, p_whh, p_whl, DD, DD);
        dim3 g1(FFH / 32, DD / 32, NL);
        transp_split_k<<<g1, blk>>>(w1, p_w1h, p_w1l, DD, FFH);
        dim3 g2(DD / 32, FFH / 32, NL);
        transp_split_k<<<g2, blk>>>(w2, p_w2h, p_w2l, FFH, DD);
    }

    // ---- patch GEMM: emb[b][d'][p] = tanh(conv_w[d',:] . im2col_b[p,:] + conv_b[d']) ----
    mgemm(conv_w, DD, 0, 0,
          nullptr, p_i2h, p_i2l, DD, (long long)SS * DD, 0,
          p_emb, SS, (long long)DD * SS, 0,
          nullptr, conv_b, 2, DD, SS, DD, BB, 1, 1.0f, 1);

    pe_add_k<<<(BSD + 255) / 256, 256>>>(p_emb, p_x);

    const long long sBS  = (long long)SS * DD;
    const long long sSCb = (long long)NH * SS * SS;
    const long long sSCh = (long long)SS * SS;
    const long long sVTb = (long long)NH * DK * SS;
    const long long sVTh = (long long)DK * SS;

    for (int l = 0; l < NL; l++) {
        long long wo = (long long)l * DD * DD;
        long long f1o = (long long)l * DD * FFH;
        const float* whbl = wh_b + (long long)l * DD;
        const float* b1l  = b1 + (long long)l * FFH;
        const float* b2l  = b2 + (long long)l * DD;

        // QKV
        mgemm(p_x, DD, 0, 0, nullptr, p_wqh + wo, p_wql + wo, DD, 0, 0,
              p_q, DD, 0, 0, nullptr, nullptr, 0, NTOK, DD, DD, 1, 1, 1.0f, 0);
        mgemm(p_x, DD, 0, 0, nullptr, p_wkh + wo, p_wkl + wo, DD, 0, 0,
              p_k, DD, 0, 0, nullptr, nullptr, 0, NTOK, DD, DD, 1, 1, 1.0f, 0);
        mgemm(p_x, DD, 0, 0, nullptr, p_wvh + wo, p_wvl + wo, DD, 0, 0,
              p_v, DD, 0, 0, nullptr, nullptr, 0, NTOK, DD, DD, 1, 1, 1.0f, 0);

        // scores = (1/8) Q Kh^T  (batched 192; A,B fp32 slices with head offset)
        mgemm(p_q, DD, sBS, DK,
              p_k, nullptr, nullptr, DD, sBS, DK,
              p_sc, SS, sSCb, sSCh,
              nullptr, nullptr, 0, SS, SS, DK, BB * NH, NH, 0.125f, 0);

        softmax_k<<<(BB * NH * SS * 32 + 255) / 256, 256>>>(p_sc, BB * NH * SS);

        // V transpose -> [z, dk, kpos] bf16 split
        {
            dim3 blk(32, 8);
            dim3 g(SS / 32, DK / 32, BB * NH);
            vtrans_k<<<g, blk>>>(p_v, p_vth, p_vtl);
        }

        // hv = A . V  (M=576, N=64, K=576, batched 192)
        mgemm(p_sc, SS, sSCb, sSCh,
              nullptr, p_vth, p_vtl, SS, sVTb, sVTh,
              p_hv, DD, sBS, DK,
              nullptr, nullptr, 0, SS, DK, SS, BB * NH, NH, 1.0f, 0);

        // x1 = hv . wh + wh_b + x
        mgemm(p_hv, DD, 0, 0, nullptr, p_whh + wo, p_whl + wo, DD, 0, 0,
              p_x1, DD, 0, 0, p_x, whbl, 1, NTOK, DD, DD, 1, 1, 1.0f, 0);

        ln_k<<<NTOK, 256>>>(p_x1, p_xn, ln2_s + (long long)l * DD, ln2_b + (long long)l * DD, 1e-6f);

        // ffh = gelu(xn . w1 + b1)
        mgemm(p_xn, DD, 0, 0, nullptr, p_w1h + f1o, p_w1l + f1o, DD, 0, 0,
              p_ffh, FFH, 0, 0, nullptr, b1l, 1, NTOK, FFH, DD, 1, 1, 1.0f, 2);

        // x = ffh . w2 + b2 + x1
        mgemm(p_ffh, FFH, 0, 0, nullptr, p_w2h + f1o, p_w2l + f1o, FFH, 0, 0,
              p_x, DD, 0, 0, p_x1, b2l, 1, NTOK, DD, FFH, 1, 1, 1.0f, 0);
    }

    ln_k<<<NTOK, 256>>>(p_x, out, lnf_s, lnf_b, 1e-12f);
}

// round 8
// speedup vs baseline: 3.3814x; 1.6099x over previous
#include <cuda_runtime.h>
#include <math.h>
#include <stdint.h>

#define BB   16
#define SS   576
#define DD   768
#define NH   12
#define DK   64
#define FFH  3072
#define NL   6
#define NTOK (BB*SS)
#define BSD  (BB*SS*DD)

typedef unsigned short u16;

// ---------------- scratch ----------------
__device__ float g_emb[BSD];
__device__ float g_x[BSD];
__device__ float g_v[BSD];
__device__ float g_x1[BSD];
__device__ float g_scores[BB*NH*SS*SS];
__device__ u16 g_i2h[BSD],  g_i2l[BSD];
__device__ u16 g_cwh[DD*DD], g_cwl[DD*DD];
__device__ u16 g_xh[BSD],  g_xl[BSD];
__device__ u16 g_qh[BSD],  g_ql[BSD];
__device__ u16 g_kh[BSD],  g_kl[BSD];
__device__ u16 g_vth[BB*NH*DK*SS], g_vtl[BB*NH*DK*SS];
__device__ u16 g_sch[BB*NH*SS*SS], g_scl[BB*NH*SS*SS];
__device__ u16 g_hvh[BSD], g_hvl[BSD];
__device__ u16 g_xnh[BSD], g_xnl[BSD];
__device__ u16 g_ffhh[NTOK*FFH], g_ffhl[NTOK*FFH];
__device__ u16 g_wqth[NL*DD*DD],  g_wqtl[NL*DD*DD];
__device__ u16 g_wkth[NL*DD*DD],  g_wktl[NL*DD*DD];
__device__ u16 g_wvth[NL*DD*DD],  g_wvtl[NL*DD*DD];
__device__ u16 g_whth[NL*DD*DD],  g_whtl[NL*DD*DD];
__device__ u16 g_w1th[NL*DD*FFH], g_w1tl[NL*DD*FFH];
__device__ u16 g_w2th[NL*DD*FFH], g_w2tl[NL*DD*FFH];

__device__ __forceinline__ uint32_t bf16rn(float x) {
    uint32_t b = __float_as_uint(x);
    return (b + 0x7FFFu + ((b >> 16) & 1u)) >> 16;
}
__device__ __forceinline__ float bfval(uint32_t h) { return __uint_as_float(h << 16); }

__device__ __forceinline__ uint32_t smem_to_u32(const void* p) {
    uint32_t a;
    asm("{ .reg .u64 t; cvta.to.shared.u64 t, %1; cvt.u32.u64 %0, t; }" : "=r"(a) : "l"(p));
    return a;
}

__device__ __forceinline__ void mma16816(float* c, const uint32_t* a, const uint32_t* b) {
    asm volatile(
        "mma.sync.aligned.m16n8k16.row.col.f32.bf16.bf16.f32 "
        "{%0,%1,%2,%3}, {%4,%5,%6,%7}, {%8,%9}, {%0,%1,%2,%3};"
        : "+f"(c[0]), "+f"(c[1]), "+f"(c[2]), "+f"(c[3])
        : "r"(a[0]), "r"(a[1]), "r"(a[2]), "r"(a[3]), "r"(b[0]), "r"(b[1]));
}

#define LDSM4(r0, r1, r2, r3, addr) \
    asm volatile("ldmatrix.sync.aligned.m8n8.x4.shared.b16 {%0,%1,%2,%3}, [%4];" \
        : "=r"(r0), "=r"(r1), "=r"(r2), "=r"(r3) : "r"(addr))

// ---------------- mma.sync GEMM (pre-split bf16 A and B) ----------------
// D[m,n] = act(alpha*(Ah+Al)[m,:].(Bh+Bl)[n,:] + bias) + res  (split-3)
#define ASTRIDE 40                   // u16 per row (80B, conflict-free ldmatrix)
#define T_AL (128*ASTRIDE)
#define T_BH (2*128*ASTRIDE)
#define T_BL (3*128*ASTRIDE)
#define STAGE_U16 (4*128*ASTRIDE)    // 20480 u16 = 40960 B
#define SMEM_DYN (2*STAGE_U16*2)     // 81920 B

__global__ __launch_bounds__(256) void mma_gemm(
    const u16* __restrict__ Ah, const u16* __restrict__ Al,
    int lda, long long sAb, long long sAh_,
    const u16* __restrict__ Bh, const u16* __restrict__ Bl,
    int ldb, long long sBb, long long sBh_,
    float* __restrict__ C, int ldc, long long sCb, long long sCh,
    const float* __restrict__ res, const float* __restrict__ bias, int biasMode,
    u16* __restrict__ Coh, u16* __restrict__ Col,
    int M, int N, int K, int nh, float alpha, int act)
{
    extern __shared__ __align__(16) u16 smem[];
    const uint32_t sbase = smem_to_u32(smem);
    const int tid = threadIdx.x;
    const int wid = tid >> 5, lane = tid & 31;
    const int wm = wid >> 2, wn = wid & 3;
    const int gid = lane >> 2, tig = lane & 3;

    int z = blockIdx.z, zb = z / nh, zh = z - zb * nh;
    const long long aoff = zb * sAb + zh * sAh_;
    const long long boff = zb * sBb + zh * sBh_;
    const long long coff = zb * sCb + zh * sCh;

    const int m0 = blockIdx.y * 128;
    const int n0 = blockIdx.x * 128;
    int validM = M - m0; if (validM > 128) validM = 128;
    int validN = N - n0; if (validN > 128) validN = 128;

    const u16* Aht = Ah + aoff + (long long)m0 * lda;
    const u16* Alt = Al + aoff + (long long)m0 * lda;
    const u16* Bht = Bh + boff + (long long)n0 * ldb;
    const u16* Blt = Bl + boff + (long long)n0 * ldb;
    const float* resT = res ? res + coff : nullptr;

    float acc[4][4][4];
    #pragma unroll
    for (int i = 0; i < 4; i++)
        #pragma unroll
        for (int j = 0; j < 4; j++)
            #pragma unroll
            for (int q = 0; q < 4; q++) acc[i][j][q] = 0.f;

    const int nC = K >> 5;
    const int rw0 = tid >> 2;
    const int kc = (tid & 3) * 8;

    auto issue = [&](int c) {
        const int k0 = c << 5;
        const uint32_t dst0 = sbase + ((c & 1) ? (uint32_t)(STAGE_U16 * 2) : 0u);
        #pragma unroll
        for (int tz = 0; tz < 4; ++tz) {
            const u16* sp = (tz == 0) ? Aht : (tz == 1) ? Alt : (tz == 2) ? Bht : Blt;
            const int ld = (tz < 2) ? lda : ldb;
            const int vr = (tz < 2) ? validM : validN;
            #pragma unroll
            for (int hf = 0; hf < 2; ++hf) {
                const int rw = hf * 64 + rw0;
                const u16* src = sp + (long long)rw * ld + k0 + kc;
                const uint32_t dst = dst0 + (uint32_t)(tz * 128 * ASTRIDE + rw * ASTRIDE + kc) * 2u;
                const uint32_t sz = (rw < vr) ? 16u : 0u;
                asm volatile("cp.async.cg.shared.global [%0], [%1], 16, %2;"
                             :: "r"(dst), "l"(src), "r"(sz));
            }
        }
        asm volatile("cp.async.commit_group;" ::: "memory");
    };

    issue(0);

    const int rA = (lane & 7) + ((lane >> 3) & 1) * 8;
    const int cA = (lane >> 4) * 8;
    const int rB = (lane & 7) + (lane >> 4) * 8;
    const int cB = ((lane >> 3) & 1) * 8;

    for (int c = 0; c < nC; ++c) {
        if (c + 1 < nC) {
            issue(c + 1);
            asm volatile("cp.async.wait_group 1;" ::: "memory");
        } else {
            asm volatile("cp.async.wait_group 0;" ::: "memory");
        }
        __syncthreads();

        const uint32_t stg = sbase + ((c & 1) ? (uint32_t)(STAGE_U16 * 2) : 0u);
        #pragma unroll
        for (int kk = 0; kk < 32; kk += 16) {
            uint32_t ah[4][4], al[4][4], bh[4][2], bl[4][2];
            #pragma unroll
            for (int i = 0; i < 4; ++i) {
                const uint32_t ad = stg + (uint32_t)(((wm * 64 + i * 16 + rA) * ASTRIDE) + kk + cA) * 2u;
                LDSM4(ah[i][0], ah[i][1], ah[i][2], ah[i][3], ad);
                LDSM4(al[i][0], al[i][1], al[i][2], al[i][3], ad + (uint32_t)(T_AL * 2));
            }
            #pragma unroll
            for (int jj = 0; jj < 2; ++jj) {
                const uint32_t bd = stg + (uint32_t)((T_BH + (wn * 32 + jj * 16 + rB) * ASTRIDE) + kk + cB) * 2u;
                LDSM4(bh[2*jj][0], bh[2*jj][1], bh[2*jj+1][0], bh[2*jj+1][1], bd);
                LDSM4(bl[2*jj][0], bl[2*jj][1], bl[2*jj+1][0], bl[2*jj+1][1],
                      bd + (uint32_t)((T_BL - T_BH) * 2));
            }
            #pragma unroll
            for (int i = 0; i < 4; ++i)
                #pragma unroll
                for (int j = 0; j < 4; ++j) mma16816(acc[i][j], ah[i], bh[j]);
            #pragma unroll
            for (int i = 0; i < 4; ++i)
                #pragma unroll
                for (int j = 0; j < 4; ++j) mma16816(acc[i][j], ah[i], bl[j]);
            #pragma unroll
            for (int i = 0; i < 4; ++i)
                #pragma unroll
                for (int j = 0; j < 4; ++j) mma16816(acc[i][j], al[i], bh[j]);
        }
        __syncthreads();
    }

    // epilogue
    #pragma unroll
    for (int i = 0; i < 4; ++i) {
        #pragma unroll
        for (int j = 0; j < 4; ++j) {
            const int col = n0 + wn * 32 + j * 8 + tig * 2;
            if (col >= N) continue;
            #pragma unroll
            for (int h = 0; h < 2; ++h) {
                const int row = m0 + wm * 64 + i * 16 + gid + h * 8;
                if (row >= M) continue;
                float vx = alpha * acc[i][j][h * 2 + 0];
                float vy = alpha * acc[i][j][h * 2 + 1];
                if (biasMode == 1) { vx += bias[col]; vy += bias[col + 1]; }
                else if (biasMode == 2) { float bm = bias[row]; vx += bm; vy += bm; }
                if (act == 1) { vx = tanhf(vx); vy = tanhf(vy); }
                else if (act == 2) {
                    const float s = 0.70710678118654752f;
                    vx = 0.5f * vx * (1.0f + erff(vx * s));
                    vy = 0.5f * vy * (1.0f + erff(vy * s));
                }
                if (resT) {
                    float2 rv = *(const float2*)(resT + (long long)row * ldc + col);
                    vx += rv.x; vy += rv.y;
                }
                const long long idx = (long long)row * ldc + col;
                if (C) {
                    float2 o; o.x = vx; o.y = vy;
                    *(float2*)(C + coff + idx) = o;
                }
                if (Coh) {
                    uint32_t h0 = bf16rn(vx), h1 = bf16rn(vy);
                    uint32_t l0 = bf16rn(vx - bfval(h0)), l1 = bf16rn(vy - bfval(h1));
                    *(uint32_t*)(Coh + coff + idx) = h0 | (h1 << 16);
                    *(uint32_t*)(Col + coff + idx) = l0 | (l1 << 16);
                }
            }
        }
    }
}

// ---------------- aux kernels ----------------
__global__ void im2col_split_k(const float* __restrict__ x,
                               u16* __restrict__ oh, u16* __restrict__ ol) {
    int i = blockIdx.x * blockDim.x + threadIdx.x;
    if (i >= BSD) return;
    int b = i / (SS * DD);
    int r = i % (SS * DD);
    int p = r / DD, k = r % DD;
    int c = k >> 8, ph = (k >> 4) & 15, pw = k & 15;
    int py = p / 24, px = p % 24;
    float v = x[(((long long)(b * 3 + c) * 384) + (py * 16 + ph)) * 384 + (px * 16 + pw)];
    uint32_t h = bf16rn(v);
    oh[i] = (u16)h;
    ol[i] = (u16)bf16rn(v - bfval(h));
}

__global__ void split_nt_k(const float* __restrict__ in,
                           u16* __restrict__ oh, u16* __restrict__ ol, int n) {
    int i = blockIdx.x * blockDim.x + threadIdx.x;
    if (i >= n) return;
    float v = in[i];
    uint32_t h = bf16rn(v);
    oh[i] = (u16)h;
    ol[i] = (u16)bf16rn(v - bfval(h));
}

// [K,N] fp32 -> [N,K] bf16 hi/lo per layer z
__global__ void transp_split_k(const float* __restrict__ in,
                               u16* __restrict__ oh, u16* __restrict__ ol,
                               int K, int N) {
    __shared__ float t[32][33];
    long long zo = (long long)blockIdx.z * K * N;
    int kb = blockIdx.y * 32, nb = blockIdx.x * 32;
    int tx = threadIdx.x, ty = threadIdx.y;
    for (int dy = ty; dy < 32; dy += 8)
        t[dy][tx] = in[zo + (long long)(kb + dy) * N + nb + tx];
    __syncthreads();
    for (int dy = ty; dy < 32; dy += 8) {
        float v = t[tx][dy];
        long long idx = zo + (long long)(nb + dy) * K + kb + tx;
        uint32_t h = bf16rn(v);
        oh[idx] = (u16)h;
        ol[idx] = (u16)bf16rn(v - bfval(h));
    }
}

// v fp32 [b, kpos, h*64+dk] -> vt bf16 [(b*NH+h), dk, kpos]
__global__ void vtrans_k(const float* __restrict__ v,
                         u16* __restrict__ oh, u16* __restrict__ ol) {
    __shared__ float t[32][33];
    int z = blockIdx.z;
    int b = z / NH, hh = z - b * NH;
    int kb = blockIdx.x * 32, db = blockIdx.y * 32;
    int tx = threadIdx.x, ty = threadIdx.y;
    for (int dy = ty; dy < 32; dy += 8)
        t[dy][tx] = v[((long long)(b * SS + kb + dy)) * DD + hh * DK + db + tx];
    __syncthreads();
    for (int dy = ty; dy < 32; dy += 8) {
        float val = t[tx][dy];
        long long idx = ((long long)z * DK + db + dy) * SS + kb + tx;
        uint32_t h = bf16rn(val);
        oh[idx] = (u16)h;
        ol[idx] = (u16)bf16rn(val - bfval(h));
    }
}

__global__ void pe_add_split_k(const float* __restrict__ emb, float* __restrict__ x,
                               u16* __restrict__ oh, u16* __restrict__ ol) {
    int i = blockIdx.x * blockDim.x + threadIdx.x;
    if (i >= BSD) return;
    int r = i % (SS * DD);
    int t = r / DD, d = r % DD;
    int j2 = (d >> 1) * 2;
    float div = expf(-(float)j2 * (9.210340371976184f / 768.0f));
    float ang = (float)t * div;
    float pe = (d & 1) ? cosf(ang) : sinf(ang);
    float v = emb[i] + pe;
    x[i] = v;
    uint32_t h = bf16rn(v);
    oh[i] = (u16)h;
    ol[i] = (u16)bf16rn(v - bfval(h));
}

__global__ void softmax_split_k(const float* __restrict__ in,
                                u16* __restrict__ oh, u16* __restrict__ ol, int rows) {
    int warp = (blockIdx.x * blockDim.x + threadIdx.x) >> 5;
    if (warp >= rows) return;
    int lane = threadIdx.x & 31;
    const float* p = in + (long long)warp * SS;
    float r[18];
    #pragma unroll
    for (int j = 0; j < 18; j++) r[j] = p[lane + j * 32];
    float mx = r[0];
    #pragma unroll
    for (int j = 1; j < 18; j++) mx = fmaxf(mx, r[j]);
    #pragma unroll
    for (int o = 16; o > 0; o >>= 1) mx = fmaxf(mx, __shfl_xor_sync(0xffffffff, mx, o));
    float sum = 0.f;
    #pragma unroll
    for (int j = 0; j < 18; j++) { r[j] = expf(r[j] - mx); sum += r[j]; }
    #pragma unroll
    for (int o = 16; o > 0; o >>= 1) sum += __shfl_xor_sync(0xffffffff, sum, o);
    float inv = 1.0f / sum;
    long long base = (long long)warp * SS;
    #pragma unroll
    for (int j = 0; j < 18; j++) {
        float v = r[j] * inv;
        uint32_t h = bf16rn(v);
        oh[base + lane + j * 32] = (u16)h;
        ol[base + lane + j * 32] = (u16)bf16rn(v - bfval(h));
    }
}

__global__ void ln_k(const float* __restrict__ in, float* __restrict__ out,
                     u16* __restrict__ oh, u16* __restrict__ ol,
                     const float* __restrict__ sc, const float* __restrict__ bi, float eps) {
    int row = blockIdx.x;
    const float* p = in + (long long)row * DD;
    int tid = threadIdx.x;
    float v0 = p[tid], v1 = p[tid + 256], v2 = p[tid + 512];
    __shared__ float red[256];
    red[tid] = v0 + v1 + v2;
    __syncthreads();
    #pragma unroll
    for (int st = 128; st > 0; st >>= 1) { if (tid < st) red[tid] += red[tid + st]; __syncthreads(); }
    float mean = red[0] * (1.0f / DD);
    __syncthreads();
    float d0 = v0 - mean, d1 = v1 - mean, d2 = v2 - mean;
    red[tid] = d0 * d0 + d1 * d1 + d2 * d2;
    __syncthreads();
    #pragma unroll
    for (int st = 128; st > 0; st >>= 1) { if (tid < st) red[tid] += red[tid + st]; __syncthreads(); }
    float inv = rsqrtf(red[0] * (1.0f / DD) + eps);
    float o0 = d0 * inv * sc[tid]       + bi[tid];
    float o1 = d1 * inv * sc[tid + 256] + bi[tid + 256];
    float o2 = d2 * inv * sc[tid + 512] + bi[tid + 512];
    long long base = (long long)row * DD;
    if (out) {
        out[base + tid] = o0; out[base + tid + 256] = o1; out[base + tid + 512] = o2;
    }
    if (oh) {
        uint32_t h0 = bf16rn(o0), h1 = bf16rn(o1), h2 = bf16rn(o2);
        oh[base + tid]       = (u16)h0; ol[base + tid]       = (u16)bf16rn(o0 - bfval(h0));
        oh[base + tid + 256] = (u16)h1; ol[base + tid + 256] = (u16)bf16rn(o1 - bfval(h1));
        oh[base + tid + 512] = (u16)h2; ol[base + tid + 512] = (u16)bf16rn(o2 - bfval(h2));
    }
}

// ---------------- host helper ----------------
static void mgemm(const u16* Ah, const u16* Al, int lda, long long sAb, long long sAh,
                  const u16* Bh, const u16* Bl, int ldb, long long sBb, long long sBhh,
                  float* C, int ldc, long long sCb, long long sCh,
                  const float* res, const float* bias, int biasMode,
                  u16* Coh, u16* Col,
                  int M, int N, int K, int batches, int nh, float alpha, int act) {
    dim3 grid((N + 127) / 128, (M + 127) / 128, batches);
    mma_gemm<<<grid, 256, SMEM_DYN>>>(Ah, Al, lda, sAb, sAh, Bh, Bl, ldb, sBb, sBhh,
                                      C, ldc, sCb, sCh, res, bias, biasMode, Coh, Col,
                                      M, N, K, nh, alpha, act);
}

extern "C" void kernel_launch(void* const* d_in, const int* in_sizes, int n_in,
                              void* d_out, int out_size) {
    const float* x      = (const float*)d_in[0];
    const float* conv_w = (const float*)d_in[1];
    const float* conv_b = (const float*)d_in[2];
    const float* wq    = (const float*)d_in[5];
    const float* wk    = (const float*)d_in[6];
    const float* wv    = (const float*)d_in[7];
    const float* wh    = (const float*)d_in[8];
    const float* wh_b  = (const float*)d_in[9];
    const float* ln2_s = (const float*)d_in[10];
    const float* ln2_b = (const float*)d_in[11];
    const float* w1    = (const float*)d_in[12];
    const float* b1    = (const float*)d_in[13];
    const float* w2    = (const float*)d_in[14];
    const float* b2    = (const float*)d_in[15];
    const float* lnf_s = (const float*)d_in[16];
    const float* lnf_b = (const float*)d_in[17];
    float* out = (float*)d_out;

    cudaFuncSetAttribute(mma_gemm, cudaFuncAttributeMaxDynamicSharedMemorySize, SMEM_DYN);

    float *p_emb, *p_x, *p_v, *p_x1, *p_sc;
    u16 *p_i2h, *p_i2l, *p_cwh, *p_cwl, *p_xh, *p_xl, *p_qh, *p_ql, *p_kh, *p_kl;
    u16 *p_vth, *p_vtl, *p_sch, *p_scl, *p_hvh, *p_hvl, *p_xnh, *p_xnl, *p_ffhh, *p_ffhl;
    u16 *p_wqh, *p_wql, *p_wkh, *p_wkl, *p_wvh, *p_wvl, *p_whh, *p_whl;
    u16 *p_w1h, *p_w1l, *p_w2h, *p_w2l;
    cudaGetSymbolAddress((void**)&p_emb, g_emb);
    cudaGetSymbolAddress((void**)&p_x,   g_x);
    cudaGetSymbolAddress((void**)&p_v,   g_v);
    cudaGetSymbolAddress((void**)&p_x1,  g_x1);
    cudaGetSymbolAddress((void**)&p_sc,  g_scores);
    cudaGetSymbolAddress((void**)&p_i2h, g_i2h);  cudaGetSymbolAddress((void**)&p_i2l, g_i2l);
    cudaGetSymbolAddress((void**)&p_cwh, g_cwh);  cudaGetSymbolAddress((void**)&p_cwl, g_cwl);
    cudaGetSymbolAddress((void**)&p_xh,  g_xh);   cudaGetSymbolAddress((void**)&p_xl,  g_xl);
    cudaGetSymbolAddress((void**)&p_qh,  g_qh);   cudaGetSymbolAddress((void**)&p_ql,  g_ql);
    cudaGetSymbolAddress((void**)&p_kh,  g_kh);   cudaGetSymbolAddress((void**)&p_kl,  g_kl);
    cudaGetSymbolAddress((void**)&p_vth, g_vth);  cudaGetSymbolAddress((void**)&p_vtl, g_vtl);
    cudaGetSymbolAddress((void**)&p_sch, g_sch);  cudaGetSymbolAddress((void**)&p_scl, g_scl);
    cudaGetSymbolAddress((void**)&p_hvh, g_hvh);  cudaGetSymbolAddress((void**)&p_hvl, g_hvl);
    cudaGetSymbolAddress((void**)&p_xnh, g_xnh);  cudaGetSymbolAddress((void**)&p_xnl, g_xnl);
    cudaGetSymbolAddress((void**)&p_ffhh, g_ffhh); cudaGetSymbolAddress((void**)&p_ffhl, g_ffhl);
    cudaGetSymbolAddress((void**)&p_wqh, g_wqth); cudaGetSymbolAddress((void**)&p_wql, g_wqtl);
    cudaGetSymbolAddress((void**)&p_wkh, g_wkth); cudaGetSymbolAddress((void**)&p_wkl, g_wktl);
    cudaGetSymbolAddress((void**)&p_wvh, g_wvth); cudaGetSymbolAddress((void**)&p_wvl, g_wvtl);
    cudaGetSymbolAddress((void**)&p_whh, g_whth); cudaGetSymbolAddress((void**)&p_whl, g_whtl);
    cudaGetSymbolAddress((void**)&p_w1h, g_w1th); cudaGetSymbolAddress((void**)&p_w1l, g_w1tl);
    cudaGetSymbolAddress((void**)&p_w2h, g_w2th); cudaGetSymbolAddress((void**)&p_w2l, g_w2tl);

    // ---- prep ----
    im2col_split_k<<<(BSD + 255) / 256, 256>>>(x, p_i2h, p_i2l);
    split_nt_k<<<(DD * DD + 255) / 256, 256>>>(conv_w, p_cwh, p_cwl, DD * DD);
    {
        dim3 blk(32, 8);
        dim3 gdd(DD / 32, DD / 32, NL);
        transp_split_k<<<gdd, blk>>>(wq, p_wqh, p_wql, DD, DD);
        transp_split_k<<<gdd, blk>>>(wk, p_wkh, p_wkl, DD, DD);
        transp_split_k<<<gdd, blk>>>(wv, p_wvh, p_wvl, DD, DD);
        transp_split_k<<<gdd, blk>>>(wh, p_whh, p_whl, DD, DD);
        dim3 g1(FFH / 32, DD / 32, NL);
        transp_split_k<<<g1, blk>>>(w1, p_w1h, p_w1l, DD, FFH);
        dim3 g2(DD / 32, FFH / 32, NL);
        transp_split_k<<<g2, blk>>>(w2, p_w2h, p_w2l, FFH, DD);
    }

    // ---- patch GEMM: emb[b][d'][p] = tanh(conv_w . im2col_b^T + conv_b) ----
    mgemm(p_cwh, p_cwl, DD, 0, 0,
          p_i2h, p_i2l, DD, (long long)SS * DD, 0,
          p_emb, SS, (long long)DD * SS, 0,
          nullptr, conv_b, 2, nullptr, nullptr,
          DD, SS, DD, BB, 1, 1.0f, 1);

    pe_add_split_k<<<(BSD + 255) / 256, 256>>>(p_emb, p_x, p_xh, p_xl);

    const long long sBS  = (long long)SS * DD;
    const long long sSCb = (long long)NH * SS * SS;
    const long long sSCh = (long long)SS * SS;
    const long long sVTb = (long long)NH * DK * SS;
    const long long sVTh = (long long)DK * SS;

    for (int l = 0; l < NL; l++) {
        long long wo = (long long)l * DD * DD;
        long long f1o = (long long)l * DD * FFH;
        const float* whbl = wh_b + (long long)l * DD;
        const float* b1l  = b1 + (long long)l * FFH;
        const float* b2l  = b2 + (long long)l * DD;

        // QKV: q,k split-only; v fp32 (for vtrans)
        mgemm(p_xh, p_xl, DD, 0, 0, p_wqh + wo, p_wql + wo, DD, 0, 0,
              nullptr, DD, 0, 0, nullptr, nullptr, 0, p_qh, p_ql,
              NTOK, DD, DD, 1, 1, 1.0f, 0);
        mgemm(p_xh, p_xl, DD, 0, 0, p_wkh + wo, p_wkl + wo, DD, 0, 0,
              nullptr, DD, 0, 0, nullptr, nullptr, 0, p_kh, p_kl,
              NTOK, DD, DD, 1, 1, 1.0f, 0);
        mgemm(p_xh, p_xl, DD, 0, 0, p_wvh + wo, p_wvl + wo, DD, 0, 0,
              p_v, DD, 0, 0, nullptr, nullptr, 0, nullptr, nullptr,
              NTOK, DD, DD, 1, 1, 1.0f, 0);

        // scores = (1/8) Q Kh^T (batched 192)
        mgemm(p_qh, p_ql, DD, sBS, DK,
              p_kh, p_kl, DD, sBS, DK,
              p_sc, SS, sSCb, sSCh,
              nullptr, nullptr, 0, nullptr, nullptr,
              SS, SS, DK, BB * NH, NH, 0.125f, 0);

        softmax_split_k<<<(BB * NH * SS * 32 + 255) / 256, 256>>>(p_sc, p_sch, p_scl, BB * NH * SS);

        {
            dim3 blk(32, 8);
            dim3 g(SS / 32, DK / 32, BB * NH);
            vtrans_k<<<g, blk>>>(p_v, p_vth, p_vtl);
        }

        // hv = probs . V (M=576,N=64,K=576, batched 192), split-only output
        mgemm(p_sch, p_scl, SS, sSCb, sSCh,
              p_vth, p_vtl, SS, sVTb, sVTh,
              nullptr, DD, sBS, DK,
              nullptr, nullptr, 0, p_hvh, p_hvl,
              SS, DK, SS, BB * NH, NH, 1.0f, 0);

        // x1 = hv . wh + wh_b + x
        mgemm(p_hvh, p_hvl, DD, 0, 0, p_whh + wo, p_whl + wo, DD, 0, 0,
              p_x1, DD, 0, 0, p_x, whbl, 1, nullptr, nullptr,
              NTOK, DD, DD, 1, 1, 1.0f, 0);

        // xn = LN(x1) -> split only
        ln_k<<<NTOK, 256>>>(p_x1, nullptr, p_xnh, p_xnl,
                            ln2_s + (long long)l * DD, ln2_b + (long long)l * DD, 1e-6f);

        // ffh = gelu(xn . w1 + b1) -> split only
        mgemm(p_xnh, p_xnl, DD, 0, 0, p_w1h + f1o, p_w1l + f1o, DD, 0, 0,
              nullptr, FFH, 0, 0, nullptr, b1l, 1, p_ffhh, p_ffhl,
              NTOK, FFH, DD, 1, 1, 1.0f, 2);

        // x = ffh . w2 + b2 + x1 -> fp32 + split (next layer input)
        mgemm(p_ffhh, p_ffhl, FFH, 0, 0, p_w2h + f1o, p_w2l + f1o, FFH, 0, 0,
              p_x, DD, 0, 0, p_x1, b2l, 1, p_xh, p_xl,
              NTOK, DD, FFH, 1, 1, 1.0f, 0);
    }

    ln_k<<<NTOK, 256>>>(p_x, out, nullptr, nullptr, lnf_s, lnf_b, 1e-12f);
}